// round 1
// baseline (speedup 1.0000x reference)
#include <cuda_runtime.h>

// Elementwise CGP model:
//   n4 = x0*x1
//   n5 = sin(n4 + c0)
//   n6 = x2*x3
//   n7 = n5*n6 + sin(x2)
//   n8 = cos(n7)*c1 + x0
//   out = [n7, n8] interleaved, shape (B, 2)
//
// B = 8388608, D = 4. Pure HBM streaming: 48 B/row.
// 2 rows per thread: 2x LDG.128 + 1x STG.128, fully coalesced.

__device__ __forceinline__ void cgp_row(float x0, float x1, float x2, float x3,
                                        float c0, float c1,
                                        float& n7, float& n8) {
    float n4 = x0 * x1;
    float n5 = sinf(n4 + c0);
    float n6 = x2 * x3;
    n7 = fmaf(n5, n6, sinf(x2));
    n8 = fmaf(cosf(n7), c1, x0);
}

__global__ void __launch_bounds__(256, 8)
cgp_kernel(const float4* __restrict__ X,
           const float* __restrict__ ephs,
           float4* __restrict__ out,
           int npairs) {
    int i = blockIdx.x * blockDim.x + threadIdx.x;
    if (i >= npairs) return;

    const float c0 = __ldg(&ephs[0]);
    const float c1 = __ldg(&ephs[1]);

    // Two rows per thread, batched loads up front for MLP=2.
    float4 a = X[2 * i];
    float4 b = X[2 * i + 1];

    float n7a, n8a, n7b, n8b;
    cgp_row(a.x, a.y, a.z, a.w, c0, c1, n7a, n8a);
    cgp_row(b.x, b.y, b.z, b.w, c0, c1, n7b, n8b);

    out[i] = make_float4(n7a, n8a, n7b, n8b);
}

extern "C" void kernel_launch(void* const* d_in, const int* in_sizes, int n_in,
                              void* d_out, int out_size) {
    const float4* X   = (const float4*)d_in[0];   // (B, 4) float32
    const float*  eph = (const float*)d_in[1];    // (2,)   float32
    float4*       out = (float4*)d_out;           // (B, 2) float32, as float4 pairs

    int B = in_sizes[0] / 4;       // rows
    int npairs = B / 2;            // 2 rows per thread

    const int TPB = 256;
    int blocks = (npairs + TPB - 1) / TPB;
    cgp_kernel<<<blocks, TPB>>>(X, eph, out, npairs);
}

// round 2
// speedup vs baseline: 1.0616x; 1.0616x over previous
#include <cuda_runtime.h>

// Elementwise CGP model, fast-math MUFU version:
//   n7 = __sinf(x0*x1 + c0) * (x2*x3) + __sinf(x2)
//   n8 = __cosf(n7)*c1 + x0
// out = [n7, n8] interleaved, shape (B, 2).
//
// B = 8388608. 48 B/row HBM traffic -> pure streaming.
// 4 rows/thread: 4x LDG.128 front-batched (MLP=4) + 2x STG.128.

__device__ __forceinline__ void cgp_row(float x0, float x1, float x2, float x3,
                                        float c0, float c1,
                                        float& n7, float& n8) {
    float n4 = __fmaf_rn(x0, x1, c0);
    float n5 = __sinf(n4);
    float n6 = x2 * x3;
    n7 = __fmaf_rn(n5, n6, __sinf(x2));
    n8 = __fmaf_rn(__cosf(n7), c1, x0);
}

__global__ void __launch_bounds__(256, 8)
cgp_kernel(const float4* __restrict__ X,
           const float* __restrict__ ephs,
           float4* __restrict__ out,
           int nquads) {
    int i = blockIdx.x * blockDim.x + threadIdx.x;
    if (i >= nquads) return;

    const float c0 = __ldg(&ephs[0]);
    const float c1 = __ldg(&ephs[1]);

    // Four rows per thread, loads batched up front for MLP=4.
    float4 a = X[4 * i + 0];
    float4 b = X[4 * i + 1];
    float4 c = X[4 * i + 2];
    float4 d = X[4 * i + 3];

    float n7a, n8a, n7b, n8b, n7c, n8c, n7d, n8d;
    cgp_row(a.x, a.y, a.z, a.w, c0, c1, n7a, n8a);
    cgp_row(b.x, b.y, b.z, b.w, c0, c1, n7b, n8b);
    cgp_row(c.x, c.y, c.z, c.w, c0, c1, n7c, n8c);
    cgp_row(d.x, d.y, d.z, d.w, c0, c1, n7d, n8d);

    out[2 * i + 0] = make_float4(n7a, n8a, n7b, n8b);
    out[2 * i + 1] = make_float4(n7c, n8c, n7d, n8d);
}

extern "C" void kernel_launch(void* const* d_in, const int* in_sizes, int n_in,
                              void* d_out, int out_size) {
    const float4* X   = (const float4*)d_in[0];   // (B, 4) float32
    const float*  eph = (const float*)d_in[1];    // (2,)   float32
    float4*       out = (float4*)d_out;           // (B, 2) float32

    int B = in_sizes[0] / 4;   // rows
    int nquads = B / 4;        // 4 rows per thread

    const int TPB = 256;
    int blocks = (nquads + TPB - 1) / TPB;
    cgp_kernel<<<blocks, TPB>>>(X, eph, out, nquads);
}

// round 3
// speedup vs baseline: 1.0793x; 1.0166x over previous
#include <cuda_runtime.h>

// Elementwise CGP model, MUFU + fully-coalesced interleaved version.
//   n7 = __sinf(x0*x1 + c0) * (x2*x3) + __sinf(x2)
//   n8 = __cosf(n7)*c1 + x0
// out = [n7, n8], shape (B, 2).
//
// Block owns 1024 consecutive rows; thread t handles rows
// {base+t, base+256+t, base+512+t, base+768+t}:
//   - each LDG.128 is lane-coalesced (16B stride -> full 128B lines)
//   - each STG.64 (float2) is lane-coalesced (8B stride -> full lines)

__device__ __forceinline__ float2 cgp_row(float4 x, float c0, float c1) {
    float n4 = __fmaf_rn(x.x, x.y, c0);
    float n5 = __sinf(n4);
    float n6 = x.z * x.w;
    float n7 = __fmaf_rn(n5, n6, __sinf(x.z));
    float n8 = __fmaf_rn(__cosf(n7), c1, x.x);
    return make_float2(n7, n8);
}

__global__ void __launch_bounds__(256, 8)
cgp_kernel(const float4* __restrict__ X,
           const float* __restrict__ ephs,
           float2* __restrict__ out) {
    const int base = blockIdx.x * 1024 + threadIdx.x;

    const float c0 = __ldg(&ephs[0]);
    const float c1 = __ldg(&ephs[1]);

    // Front-batched coalesced loads, MLP=4.
    float4 a = X[base + 0];
    float4 b = X[base + 256];
    float4 c = X[base + 512];
    float4 d = X[base + 768];

    float2 ra = cgp_row(a, c0, c1);
    float2 rb = cgp_row(b, c0, c1);
    float2 rc = cgp_row(c, c0, c1);
    float2 rd = cgp_row(d, c0, c1);

    out[base + 0]   = ra;
    out[base + 256] = rb;
    out[base + 512] = rc;
    out[base + 768] = rd;
}

extern "C" void kernel_launch(void* const* d_in, const int* in_sizes, int n_in,
                              void* d_out, int out_size) {
    const float4* X   = (const float4*)d_in[0];   // (B, 4) float32, one float4/row
    const float*  eph = (const float*)d_in[1];    // (2,)   float32
    float2*       out = (float2*)d_out;           // (B, 2) float32, one float2/row

    int B = in_sizes[0] / 4;       // rows = 8388608
    int blocks = B / 1024;         // 1024 rows per block (B divisible)

    cgp_kernel<<<blocks, 256>>>(X, eph, out);
}